// round 3
// baseline (speedup 1.0000x reference)
#include <cuda_runtime.h>
#include <stdint.h>

#define NPT  64
#define NC   500000
#define NC4  (NC/4)      // 125000 float4 columns
#define NANG 2016        // 64*63/2

// g_Mt[k*64 + i] = mus[i] * M[i][k]   (M = product of Givens rotations)
__device__ __align__(16) float g_Mt[NPT * NPT];

// ---------------------------------------------------------------------------
// Kernel 1: build the composite 64x64 rotation matrix.
// One thread per column of M; rotation schedule fully unrolled with
// compile-time indices so m[64] stays in registers.
// ---------------------------------------------------------------------------
__global__ void __launch_bounds__(64) build_M_kernel(const float* __restrict__ angles,
                                                     const float* __restrict__ mus) {
    __shared__ float sc[NANG];
    __shared__ float ss[NANG];
    const int t = threadIdx.x;

    // Phase A: precompute all cos/sin in parallel.
    for (int a = t; a < NANG; a += 64) {
        float s, c;
        sincosf(angles[a], &s, &c);
        sc[a] = c;
        ss[a] = s;
    }
    __syncthreads();

    // Phase B: thread t owns column t of M. Apply all 2016 rotations.
    float m[NPT];
#pragma unroll
    for (int i = 0; i < NPT; ++i) m[i] = (i == t) ? 1.0f : 0.0f;

    int a = 0;
#pragma unroll
    for (int it = 0; it < NPT - 1; ++it) {
#pragma unroll
        for (int ib = it + 1; ib < NPT; ++ib) {
            const float c = sc[a];
            const float s = ss[a];
            ++a;
            const float vt = m[it];
            const float vb = m[ib];
            m[it] = fmaf(c, vt, -s * vb);
            m[ib] = fmaf(s, vt,  c * vb);
        }
    }

    // Store transposed (k-major) with mus folded in.
#pragma unroll
    for (int i = 0; i < NPT; ++i) g_Mt[t * NPT + i] = m[i] * __ldg(&mus[i]);
}

// ---------------------------------------------------------------------------
// Packed f32x2 helpers (FFMA2 — 2x FP32 FMA throughput; ptxas won't emit this
// from plain C++). Packed pairs live in unsigned long long ("l" constraint).
// ---------------------------------------------------------------------------
typedef unsigned long long u64;

__device__ __forceinline__ u64 ffma2(u64 a, u64 b, u64 c) {
    u64 d;
    asm("fma.rn.f32x2 %0, %1, %2, %3;" : "=l"(d) : "l"(a), "l"(b), "l"(c));
    return d;
}
__device__ __forceinline__ u64 pack2(float lo, float hi) {
    u64 d;
    asm("mov.b64 %0, {%1, %2};" : "=l"(d) : "f"(lo), "f"(hi));
    return d;
}
__device__ __forceinline__ void unpack2(u64 d, float& lo, float& hi) {
    asm("mov.b64 {%0, %1}, %2;" : "=f"(lo), "=f"(hi) : "l"(d));
}

// ---------------------------------------------------------------------------
// Kernel 2: Y = (diag(mus)*M) @ X,  X: [64, 500000] row-major fp32.
// Block: 256 threads. tx in [0,64) -> one float4 column group (256 fp32 cols
// per block, coalesced). ty in [0,4) -> 16 output rows.
// Accumulators: 8 row-pairs x 4 cols as f32x2 (rows packed -> M operand comes
// pre-packed from shared via 128-bit loads; X value replicated per column).
// ---------------------------------------------------------------------------
__global__ void __launch_bounds__(256) gemm_kernel(const float4* __restrict__ X,
                                                   float4* __restrict__ Y) {
    __shared__ __align__(16) float sM[NPT * NPT];

    const int tid = threadIdx.x;
    // cooperative load of M (4096 floats = 1024 float4)
#pragma unroll
    for (int i = 0; i < 4; ++i)
        ((float4*)sM)[tid + i * 256] = ((const float4*)g_Mt)[tid + i * 256];
    __syncthreads();

    const int tx = tid & 63;
    const int ty = tid >> 6;                 // row block: rows [ty*16, ty*16+16)
    const long c4 = (long)blockIdx.x * 64 + tx;
    if (c4 >= NC4) return;                   // tail block (no syncs after this)

    const float4* xp = X + c4;

    u64 acc[8][4];
#pragma unroll
    for (int p = 0; p < 8; ++p)
#pragma unroll
        for (int c = 0; c < 4; ++c) acc[p][c] = 0ULL;  // bit pattern = (0.f, 0.f)

#pragma unroll 8
    for (int k = 0; k < NPT; ++k) {
        const float4 xv = __ldg(xp + (long)k * NC4);
        const u64 x0 = pack2(xv.x, xv.x);
        const u64 x1 = pack2(xv.y, xv.y);
        const u64 x2 = pack2(xv.z, xv.z);
        const u64 x3 = pack2(xv.w, xv.w);

        const ulonglong2* mp = (const ulonglong2*)&sM[k * NPT + ty * 16];
#pragma unroll
        for (int pq = 0; pq < 4; ++pq) {
            const ulonglong2 md = mp[pq];    // LDS.128: rows (4pq..4pq+3) packed
            const int p0 = 2 * pq;
            acc[p0][0]   = ffma2(md.x, x0, acc[p0][0]);
            acc[p0][1]   = ffma2(md.x, x1, acc[p0][1]);
            acc[p0][2]   = ffma2(md.x, x2, acc[p0][2]);
            acc[p0][3]   = ffma2(md.x, x3, acc[p0][3]);
            acc[p0+1][0] = ffma2(md.y, x0, acc[p0+1][0]);
            acc[p0+1][1] = ffma2(md.y, x1, acc[p0+1][1]);
            acc[p0+1][2] = ffma2(md.y, x2, acc[p0+1][2]);
            acc[p0+1][3] = ffma2(md.y, x3, acc[p0+1][3]);
        }
    }

    float4* yp = Y + c4;
#pragma unroll
    for (int p = 0; p < 8; ++p) {
        float a0, b0, a1, b1, a2, b2, a3, b3;
        unpack2(acc[p][0], a0, b0);
        unpack2(acc[p][1], a1, b1);
        unpack2(acc[p][2], a2, b2);
        unpack2(acc[p][3], a3, b3);
        const int r0 = ty * 16 + 2 * p;
        yp[(long)r0 * NC4]       = make_float4(a0, a1, a2, a3);
        yp[(long)(r0 + 1) * NC4] = make_float4(b0, b1, b2, b3);
    }
}

// ---------------------------------------------------------------------------
extern "C" void kernel_launch(void* const* d_in, const int* in_sizes, int n_in,
                              void* d_out, int out_size) {
    const float* X      = (const float*)d_in[0];
    const float* angles = (const float*)d_in[1];
    const float* mus    = (const float*)d_in[2];
    float* Y = (float*)d_out;

    build_M_kernel<<<1, 64>>>(angles, mus);

    const int grid = (NC4 + 63) / 64;   // 1954
    gemm_kernel<<<grid, 256>>>((const float4*)X, (float4*)Y);
}

// round 4
// speedup vs baseline: 1.7716x; 1.7716x over previous
#include <cuda_runtime.h>
#include <stdint.h>

#define NPT  64
#define NC   500000
#define NC4  125000      // NC/4 float4 columns
#define NANG 2016        // 64*63/2
#define KC   8           // k-rows per cp.async chunk
#define NBUF 3           // pipeline depth
#define NCHUNK (NPT/KC)  // 8

// g_Mt[k*64 + i] = mus[i] * M[i][k]   (M = product of Givens rotations)
__device__ __align__(16) float g_Mt[NPT * NPT];

// ---------------------------------------------------------------------------
// Kernel 1: build the composite 64x64 rotation matrix.
// ROLLED loop (v1's fully-unrolled version was ~130KB of code -> I$-bound,
// ~96us). Matrix lives in shared (sm[row][col], lane=col: conflict-free);
// vt is register-carried across the inner loop so the serial chain is just
// FMA latency (~2016 x 9 cyc ~= 10us).
// ---------------------------------------------------------------------------
__global__ void __launch_bounds__(64) build_M_kernel(const float* __restrict__ angles,
                                                     const float* __restrict__ mus) {
    __shared__ float sc[NANG];
    __shared__ float ss[NANG];
    __shared__ float sm[NPT][NPT];   // [row][col]
    const int t = threadIdx.x;

    for (int a = t; a < NANG; a += 64) {
        float s, c;
        sincosf(angles[a], &s, &c);
        sc[a] = c;
        ss[a] = s;
    }
    for (int i = 0; i < NPT; ++i) sm[i][t] = (i == t) ? 1.0f : 0.0f;
    __syncthreads();

    int a = 0;
    for (int it = 0; it < NPT - 1; ++it) {
        float vt = sm[it][t];
        for (int ib = it + 1; ib < NPT; ++ib) {
            const float c = sc[a];
            const float s = ss[a];
            ++a;
            const float vb = sm[ib][t];
            sm[ib][t] = fmaf(s, vt, c * vb);
            vt = fmaf(c, vt, -s * vb);
        }
        sm[it][t] = vt;
    }
    // thread t wrote column t; it alone reads it back -> no sync needed.
    for (int i = 0; i < NPT; ++i) g_Mt[t * NPT + i] = sm[i][t] * __ldg(&mus[i]);
}

// ---------------------------------------------------------------------------
// Packed f32x2 helpers (FFMA2).
// ---------------------------------------------------------------------------
typedef unsigned long long u64;

__device__ __forceinline__ u64 ffma2(u64 a, u64 b, u64 c) {
    u64 d;
    asm("fma.rn.f32x2 %0, %1, %2, %3;" : "=l"(d) : "l"(a), "l"(b), "l"(c));
    return d;
}
__device__ __forceinline__ u64 pack2(float lo, float hi) {
    u64 d;
    asm("mov.b64 %0, {%1, %2};" : "=l"(d) : "f"(lo), "f"(hi));
    return d;
}
__device__ __forceinline__ void unpack2(u64 d, float& lo, float& hi) {
    asm("mov.b64 {%0, %1}, %2;" : "=f"(lo), "=f"(hi) : "l"(d));
}

// ---------------------------------------------------------------------------
// cp.async helpers
// ---------------------------------------------------------------------------
__device__ __forceinline__ void cp_async16(uint32_t smem_dst, const void* gsrc, int src_bytes) {
    asm volatile("cp.async.cg.shared.global [%0], [%1], 16, %2;"
                 :: "r"(smem_dst), "l"(gsrc), "r"(src_bytes));
}
__device__ __forceinline__ void cp_commit() {
    asm volatile("cp.async.commit_group;");
}

// Issue one KC x 64-float4 chunk (16KB/2 = 8KB) : 2 cp.async per thread.
__device__ __forceinline__ void issue_chunk(const float4* __restrict__ X,
                                            float4 (*sX)[KC][64],
                                            long cb, int tid, int ch, int buf) {
#pragma unroll
    for (int r = 0; r < 2; ++r) {
        const int e = tid + r * 256;
        const int k = e >> 6;
        const int c = e & 63;
        const long col = cb + c;
        const bool ok = (col < NC4);
        const float4* src = X + (long)(ch * KC + k) * NC4 + (ok ? col : 0);
        const uint32_t dst = (uint32_t)__cvta_generic_to_shared(&sX[buf][k][c]);
        cp_async16(dst, src, ok ? 16 : 0);   // zfill on OOB columns
    }
    cp_commit();
}

// ---------------------------------------------------------------------------
// Kernel 2: Y = (diag(mus)*M) @ X.
// Block: 256 threads. tx in [0,64) -> one float4 column group; ty in [0,4)
// -> 16 output rows. X staged via 3-deep cp.async pipeline; M loads are
// warp-broadcast LDS.128.
// ---------------------------------------------------------------------------
__global__ void __launch_bounds__(256) gemm_kernel(const float4* __restrict__ X,
                                                   float4* __restrict__ Y) {
    __shared__ __align__(16) float  sM[NPT * NPT];        // 16 KB
    __shared__ __align__(16) float4 sX[NBUF][KC][64];     // 24 KB

    const int tid = threadIdx.x;
#pragma unroll
    for (int i = 0; i < 4; ++i)
        ((float4*)sM)[tid + i * 256] = ((const float4*)g_Mt)[tid + i * 256];

    const int tx = tid & 63;
    const int ty = tid >> 6;
    const long cb = (long)blockIdx.x * 64;
    const long c4 = cb + tx;
    const bool colok = (c4 < NC4);

    issue_chunk(X, sX, cb, tid, 0, 0);
    issue_chunk(X, sX, cb, tid, 1, 1);

    u64 acc[8][4];
#pragma unroll
    for (int p = 0; p < 8; ++p)
#pragma unroll
        for (int c = 0; c < 4; ++c) acc[p][c] = 0ULL;

    for (int ch = 0; ch < NCHUNK; ++ch) {
        const int nxt = ch + NBUF - 1;
        if (nxt < NCHUNK) issue_chunk(X, sX, cb, tid, nxt, nxt % NBUF);
        else              cp_commit();     // empty group keeps the count aligned
        asm volatile("cp.async.wait_group %0;" :: "n"(NBUF - 1));
        __syncthreads();                   // chunk ch landed for all warps (also covers sM on ch=0)

        const int buf = ch % NBUF;
#pragma unroll
        for (int k = 0; k < KC; ++k) {
            const float4 xv = sX[buf][k][tx];
            const u64 x0 = pack2(xv.x, xv.x);
            const u64 x1 = pack2(xv.y, xv.y);
            const u64 x2 = pack2(xv.z, xv.z);
            const u64 x3 = pack2(xv.w, xv.w);

            const ulonglong2* mp = (const ulonglong2*)&sM[(ch * KC + k) * NPT + ty * 16];
#pragma unroll
            for (int pq = 0; pq < 4; ++pq) {
                const ulonglong2 md = mp[pq];    // broadcast LDS.128: rows 4pq..4pq+3
                const int p0 = 2 * pq;
                acc[p0][0]   = ffma2(md.x, x0, acc[p0][0]);
                acc[p0][1]   = ffma2(md.x, x1, acc[p0][1]);
                acc[p0][2]   = ffma2(md.x, x2, acc[p0][2]);
                acc[p0][3]   = ffma2(md.x, x3, acc[p0][3]);
                acc[p0+1][0] = ffma2(md.y, x0, acc[p0+1][0]);
                acc[p0+1][1] = ffma2(md.y, x1, acc[p0+1][1]);
                acc[p0+1][2] = ffma2(md.y, x2, acc[p0+1][2]);
                acc[p0+1][3] = ffma2(md.y, x3, acc[p0+1][3]);
            }
        }
        __syncthreads();                   // all warps done reading buf before it is re-issued
    }

    if (colok) {
        float4* yp = Y + c4;
#pragma unroll
        for (int p = 0; p < 8; ++p) {
            float a0, b0, a1, b1, a2, b2, a3, b3;
            unpack2(acc[p][0], a0, b0);
            unpack2(acc[p][1], a1, b1);
            unpack2(acc[p][2], a2, b2);
            unpack2(acc[p][3], a3, b3);
            const int r0 = ty * 16 + 2 * p;
            yp[(long)r0 * NC4]       = make_float4(a0, a1, a2, a3);
            yp[(long)(r0 + 1) * NC4] = make_float4(b0, b1, b2, b3);
        }
    }
}

// ---------------------------------------------------------------------------
extern "C" void kernel_launch(void* const* d_in, const int* in_sizes, int n_in,
                              void* d_out, int out_size) {
    const float* X      = (const float*)d_in[0];
    const float* angles = (const float*)d_in[1];
    const float* mus    = (const float*)d_in[2];
    float* Y = (float*)d_out;

    build_M_kernel<<<1, 64>>>(angles, mus);

    const int grid = (NC4 + 63) / 64;   // 1954
    gemm_kernel<<<grid, 256>>>((const float4*)X, (float4*)Y);
}

// round 7
// speedup vs baseline: 1.8439x; 1.0408x over previous
#include <cuda_runtime.h>
#include <stdint.h>

#define NPT  64
#define NC   500000
#define NC4  125000      // NC/4 float4 columns
#define NANG 2016        // 64*63/2
#define KC   16          // k-rows per cp.async chunk
#define NBUF 3           // pipeline depth
#define NCHUNK (NPT/KC)  // 4

// g_Mt[k*64 + i] = mus[i] * M[i][k]
__device__ __align__(16) float g_Mt[NPT * NPT];

// ---------------------------------------------------------------------------
// Kernel 1: build the composite 64x64 rotation matrix.
// Rolled loop, but with the sm[ib] load PREFETCHED one iteration ahead into a
// register before the store, so the LDS latency (29cyc) and the st->ld
// alias-serialization are off the serial FMA chain. Chain ~= 2016 x 4cyc.
// ---------------------------------------------------------------------------
__global__ void __launch_bounds__(64) build_M_kernel(const float* __restrict__ angles,
                                                     const float* __restrict__ mus) {
    __shared__ float sc[NANG];
    __shared__ float ss[NANG];
    __shared__ float sm[NPT][NPT];   // [row][col]
    const int t = threadIdx.x;

    for (int a = t; a < NANG; a += 64) {
        float s, c;
        sincosf(angles[a], &s, &c);
        sc[a] = c;
        ss[a] = s;
    }
    for (int i = 0; i < NPT; ++i) sm[i][t] = (i == t) ? 1.0f : 0.0f;
    __syncthreads();

    int a = 0;
    for (int it = 0; it < NPT - 1; ++it) {
        float vt = sm[it][t];
        float vb = sm[it + 1][t];
#pragma unroll 7
        for (int ib = it + 1; ib < NPT - 1; ++ib) {
            const float c = sc[a];
            const float s = ss[a];
            ++a;
            const float vbn = sm[ib + 1][t];   // prefetch BEFORE the store
            sm[ib][t] = fmaf(s, vt, c * vb);   // off-chain
            vt = fmaf(c, vt, -s * vb);         // the only chain op
            vb = vbn;
        }
        {   // last rotation of the pass (ib = NPT-1)
            const float c = sc[a];
            const float s = ss[a];
            ++a;
            sm[NPT - 1][t] = fmaf(s, vt, c * vb);
            vt = fmaf(c, vt, -s * vb);
        }
        sm[it][t] = vt;
    }
    // thread t wrote column t; it alone reads it back -> no sync needed.
    for (int i = 0; i < NPT; ++i) g_Mt[t * NPT + i] = sm[i][t] * __ldg(&mus[i]);
}

// ---------------------------------------------------------------------------
// Packed f32x2 helpers (FFMA2).
// ---------------------------------------------------------------------------
typedef unsigned long long u64;

__device__ __forceinline__ u64 ffma2(u64 a, u64 b, u64 c) {
    u64 d;
    asm("fma.rn.f32x2 %0, %1, %2, %3;" : "=l"(d) : "l"(a), "l"(b), "l"(c));
    return d;
}
__device__ __forceinline__ u64 pack2(float lo, float hi) {
    u64 d;
    asm("mov.b64 %0, {%1, %2};" : "=l"(d) : "f"(lo), "f"(hi));
    return d;
}
__device__ __forceinline__ void unpack2(u64 d, float& lo, float& hi) {
    asm("mov.b64 {%0, %1}, %2;" : "=f"(lo), "=f"(hi) : "l"(d));
}

// ---------------------------------------------------------------------------
// cp.async helpers
// ---------------------------------------------------------------------------
__device__ __forceinline__ void cp_async16(uint32_t smem_dst, const void* gsrc, int src_bytes) {
    asm volatile("cp.async.cg.shared.global [%0], [%1], 16, %2;"
                 :: "r"(smem_dst), "l"(gsrc), "r"(src_bytes));
}
__device__ __forceinline__ void cp_commit() {
    asm volatile("cp.async.commit_group;");
}

// Issue one KC x 64-float4 chunk (16KB): 4 cp.async per thread.
__device__ __forceinline__ void issue_chunk(const float4* __restrict__ X,
                                            float4 (*sX)[KC][64],
                                            long cb, int tid, int ch, int buf) {
#pragma unroll
    for (int r = 0; r < (KC * 64) / 256; ++r) {
        const int e = tid + r * 256;
        const int k = e >> 6;
        const int c = e & 63;
        const long col = cb + c;
        const bool ok = (col < NC4);
        const float4* src = X + (long)(ch * KC + k) * NC4 + (ok ? col : 0);
        const uint32_t dst = (uint32_t)__cvta_generic_to_shared(&sX[buf][k][c]);
        cp_async16(dst, src, ok ? 16 : 0);   // zfill on OOB columns
    }
    cp_commit();
}

// ---------------------------------------------------------------------------
// Kernel 2: Y = (diag(mus)*M) @ X.
// 256 threads: tx in [0,64) -> float4 column group; ty in [0,4) -> 16 rows.
// One __syncthreads per chunk: wait -> sync -> issue ordering makes the single
// barrier cover both "chunk ch visible to all" and "all done reading the
// buffer being overwritten".
// ---------------------------------------------------------------------------
__global__ void __launch_bounds__(256) gemm_kernel(const float4* __restrict__ X,
                                                   float4* __restrict__ Y) {
    __shared__ __align__(16) float  sM[NPT * NPT];        // 16 KB
    __shared__ __align__(16) float4 sX[NBUF][KC][64];     // 48 KB

    const int tid = threadIdx.x;
#pragma unroll
    for (int i = 0; i < 4; ++i)
        ((float4*)sM)[tid + i * 256] = ((const float4*)g_Mt)[tid + i * 256];

    const int tx = tid & 63;
    const int ty = tid >> 6;
    const long cb = (long)blockIdx.x * 64;
    const long c4 = cb + tx;
    const bool colok = (c4 < NC4);

    issue_chunk(X, sX, cb, tid, 0, 0);
    issue_chunk(X, sX, cb, tid, 1, 1);

    u64 acc[8][4];
#pragma unroll
    for (int p = 0; p < 8; ++p)
#pragma unroll
        for (int c = 0; c < 4; ++c) acc[p][c] = 0ULL;

    for (int ch = 0; ch < NCHUNK; ++ch) {
        // chunk ch's group complete (all but most recent NBUF-2 groups drained)
        asm volatile("cp.async.wait_group %0;" :: "n"(NBUF - 2));
        __syncthreads();   // ch visible to all; all threads done reading buf (ch-1)%NBUF

        const int nxt = ch + NBUF - 1;
        if (nxt < NCHUNK) issue_chunk(X, sX, cb, tid, nxt, nxt % NBUF);
        else              cp_commit();     // empty group keeps wait counts aligned

        const int buf = ch % NBUF;
#pragma unroll
        for (int k = 0; k < KC; ++k) {
            const float4 xv = sX[buf][k][tx];
            const u64 x0 = pack2(xv.x, xv.x);
            const u64 x1 = pack2(xv.y, xv.y);
            const u64 x2 = pack2(xv.z, xv.z);
            const u64 x3 = pack2(xv.w, xv.w);

            const ulonglong2* mp = (const ulonglong2*)&sM[(ch * KC + k) * NPT + ty * 16];
#pragma unroll
            for (int pq = 0; pq < 4; ++pq) {
                const ulonglong2 md = mp[pq];    // broadcast LDS.128: rows 4pq..4pq+3
                const int p0 = 2 * pq;
                acc[p0][0]   = ffma2(md.x, x0, acc[p0][0]);
                acc[p0][1]   = ffma2(md.x, x1, acc[p0][1]);
                acc[p0][2]   = ffma2(md.x, x2, acc[p0][2]);
                acc[p0][3]   = ffma2(md.x, x3, acc[p0][3]);
                acc[p0+1][0] = ffma2(md.y, x0, acc[p0+1][0]);
                acc[p0+1][1] = ffma2(md.y, x1, acc[p0+1][1]);
                acc[p0+1][2] = ffma2(md.y, x2, acc[p0+1][2]);
                acc[p0+1][3] = ffma2(md.y, x3, acc[p0+1][3]);
            }
        }
    }

    if (colok) {
        float4* yp = Y + c4;
#pragma unroll
        for (int p = 0; p < 8; ++p) {
            float a0, b0, a1, b1, a2, b2, a3, b3;
            unpack2(acc[p][0], a0, b0);
            unpack2(acc[p][1], a1, b1);
            unpack2(acc[p][2], a2, b2);
            unpack2(acc[p][3], a3, b3);
            const int r0 = ty * 16 + 2 * p;
            yp[(long)r0 * NC4]       = make_float4(a0, a1, a2, a3);
            yp[(long)(r0 + 1) * NC4] = make_float4(b0, b1, b2, b3);
        }
    }
}

// ---------------------------------------------------------------------------
extern "C" void kernel_launch(void* const* d_in, const int* in_sizes, int n_in,
                              void* d_out, int out_size) {
    const float* X      = (const float*)d_in[0];
    const float* angles = (const float*)d_in[1];
    const float* mus    = (const float*)d_in[2];
    float* Y = (float*)d_out;

    build_M_kernel<<<1, 64>>>(angles, mus);

    const int grid = (NC4 + 63) / 64;   // 1954
    gemm_kernel<<<grid, 256>>>((const float4*)X, (float4*)Y);
}

// round 10
// speedup vs baseline: 2.0079x; 1.0889x over previous
#include <cuda_runtime.h>
#include <stdint.h>

#define NPT  64
#define NC   500000
#define NC4  125000      // NC/4 float4 columns
#define NANG 2016        // 64*63/2
#define KC   16          // k-rows per cp.async chunk
#define NBUF 3           // pipeline depth
#define NCHUNK (NPT/KC)  // 4
#define CW   32          // float4 columns per block

// g_Mt[k*64 + i] = mus[i] * M[i][k]
__device__ __align__(16) float g_Mt[NPT * NPT];

// ---------------------------------------------------------------------------
// Kernel 1: build the composite 64x64 rotation matrix.
// Depth-4 register prefetch for BOTH the row value (vb) and the (cos,sin)
// pair, so the 29-cyc LDS latency is fully covered by ~40 cyc of issue slack;
// the serial chain is just the 4-cyc FFMA on vt.
// ---------------------------------------------------------------------------
__global__ void __launch_bounds__(64) build_M_kernel(const float* __restrict__ angles,
                                                     const float* __restrict__ mus) {
    __shared__ float2 scs[NANG];     // (cos, sin) fused -> one LDS.64
    __shared__ float  sm[NPT][NPT];  // [row][col]
    const int t = threadIdx.x;

    for (int a = t; a < NANG; a += 64) {
        float s, c;
        sincosf(angles[a], &s, &c);
        scs[a] = make_float2(c, s);
    }
    for (int i = 0; i < NPT; ++i) sm[i][t] = (i == t) ? 1.0f : 0.0f;
    __syncthreads();

    int a = 0;
    for (int it = 0; it < NPT - 1; ++it) {
        const int len = NPT - 1 - it;
        float vt = sm[it][t];
        // prime depth-4 prefetch (clamped at pass end / table end)
        float vb0 = sm[it + 1][t];
        float vb1 = (len > 1) ? sm[it + 2][t] : 0.0f;
        float vb2 = (len > 2) ? sm[it + 3][t] : 0.0f;
        float vb3 = (len > 3) ? sm[it + 4][t] : 0.0f;
        float2 cs0 = scs[a];
        float2 cs1 = (a + 1 < NANG) ? scs[a + 1] : make_float2(1.f, 0.f);
        float2 cs2 = (a + 2 < NANG) ? scs[a + 2] : make_float2(1.f, 0.f);
        float2 cs3 = (a + 3 < NANG) ? scs[a + 3] : make_float2(1.f, 0.f);

#pragma unroll 4
        for (int ib = it + 1; ib < NPT; ++ib) {
            const float c = cs0.x;
            const float s = cs0.y;
            const float vb = vb0;
            // rotate prefetch buffers (renamed away under unroll)
            vb0 = vb1; vb1 = vb2; vb2 = vb3;
            cs0 = cs1; cs1 = cs2; cs2 = cs3;
            const int pf = ib + 4;
            vb3 = (pf < NPT) ? sm[pf][t] : 0.0f;
            const int apf = a + 4;
            cs3 = (apf < NANG) ? scs[apf] : make_float2(1.f, 0.f);

            sm[ib][t] = fmaf(s, vt, c * vb);   // off-chain
            vt = fmaf(c, vt, -s * vb);         // 4-cyc chain
            ++a;
        }
        sm[it][t] = vt;
    }
    // thread t wrote column t; it alone reads it back -> no sync needed.
    for (int i = 0; i < NPT; ++i) g_Mt[t * NPT + i] = sm[i][t] * __ldg(&mus[i]);
}

// ---------------------------------------------------------------------------
// Packed f32x2 helpers (FFMA2).
// ---------------------------------------------------------------------------
typedef unsigned long long u64;

__device__ __forceinline__ u64 ffma2(u64 a, u64 b, u64 c) {
    u64 d;
    asm("fma.rn.f32x2 %0, %1, %2, %3;" : "=l"(d) : "l"(a), "l"(b), "l"(c));
    return d;
}
__device__ __forceinline__ u64 pack2(float lo, float hi) {
    u64 d;
    asm("mov.b64 %0, {%1, %2};" : "=l"(d) : "f"(lo), "f"(hi));
    return d;
}
__device__ __forceinline__ void unpack2(u64 d, float& lo, float& hi) {
    asm("mov.b64 {%0, %1}, %2;" : "=f"(lo), "=f"(hi) : "l"(d));
}

// ---------------------------------------------------------------------------
// cp.async helpers
// ---------------------------------------------------------------------------
__device__ __forceinline__ void cp_async16(uint32_t smem_dst, const void* gsrc, int src_bytes) {
    asm volatile("cp.async.cg.shared.global [%0], [%1], 16, %2;"
                 :: "r"(smem_dst), "l"(gsrc), "r"(src_bytes));
}
__device__ __forceinline__ void cp_commit() {
    asm volatile("cp.async.commit_group;");
}

// Issue one KC x CW-float4 chunk (8KB): 2 cp.async per thread.
__device__ __forceinline__ void issue_chunk(const float4* __restrict__ X,
                                            float4 (*sX)[KC][CW],
                                            long cb, int tid, int ch, int buf) {
#pragma unroll
    for (int r = 0; r < (KC * CW) / 256; ++r) {
        const int e = tid + r * 256;
        const int k = e / CW;
        const int c = e % CW;
        const long col = cb + c;
        const bool ok = (col < NC4);
        const float4* src = X + (long)(ch * KC + k) * NC4 + (ok ? col : 0);
        const uint32_t dst = (uint32_t)__cvta_generic_to_shared(&sX[buf][k][c]);
        cp_async16(dst, src, ok ? 16 : 0);   // zfill on OOB columns
    }
    cp_commit();
}

// ---------------------------------------------------------------------------
// Kernel 2: Y = (diag(mus)*M) @ X.
// 256 threads: tx in [0,32) -> float4 column; ty in [0,8) -> 8 output rows
// (4 row-pairs). 16 u64 accumulators/thread -> ~70 regs -> 3 blocks/SM
// (24 warps) for latency hiding. Warp = one ty -> M loads broadcast.
// ---------------------------------------------------------------------------
__global__ void __launch_bounds__(256, 3) gemm_kernel(const float4* __restrict__ X,
                                                      float4* __restrict__ Y) {
    __shared__ __align__(16) float  sM[NPT * NPT];        // 16 KB
    __shared__ __align__(16) float4 sX[NBUF][KC][CW];     // 24 KB

    const int tid = threadIdx.x;
#pragma unroll
    for (int i = 0; i < 4; ++i)
        ((float4*)sM)[tid + i * 256] = ((const float4*)g_Mt)[tid + i * 256];

    const int tx = tid & 31;
    const int ty = tid >> 5;                 // rows [ty*8, ty*8+8)
    const long cb = (long)blockIdx.x * CW;
    const long c4 = cb + tx;
    const bool colok = (c4 < NC4);

    issue_chunk(X, sX, cb, tid, 0, 0);
    issue_chunk(X, sX, cb, tid, 1, 1);

    u64 acc[4][4];
#pragma unroll
    for (int p = 0; p < 4; ++p)
#pragma unroll
        for (int c = 0; c < 4; ++c) acc[p][c] = 0ULL;

    for (int ch = 0; ch < NCHUNK; ++ch) {
        asm volatile("cp.async.wait_group %0;" :: "n"(NBUF - 2));
        __syncthreads();   // ch visible to all; all done reading buf (ch-1)%NBUF

        const int nxt = ch + NBUF - 1;
        if (nxt < NCHUNK) issue_chunk(X, sX, cb, tid, nxt, nxt % NBUF);
        else              cp_commit();     // empty group keeps wait counts aligned

        const int buf = ch % NBUF;
#pragma unroll
        for (int k = 0; k < KC; ++k) {
            const float4 xv = sX[buf][k][tx];
            const u64 x0 = pack2(xv.x, xv.x);
            const u64 x1 = pack2(xv.y, xv.y);
            const u64 x2 = pack2(xv.z, xv.z);
            const u64 x3 = pack2(xv.w, xv.w);

            const ulonglong2* mp = (const ulonglong2*)&sM[(ch * KC + k) * NPT + ty * 8];
#pragma unroll
            for (int pq = 0; pq < 2; ++pq) {
                const ulonglong2 md = mp[pq];    // broadcast LDS.128: rows 4pq..4pq+3
                const int p0 = 2 * pq;
                acc[p0][0]   = ffma2(md.x, x0, acc[p0][0]);
                acc[p0][1]   = ffma2(md.x, x1, acc[p0][1]);
                acc[p0][2]   = ffma2(md.x, x2, acc[p0][2]);
                acc[p0][3]   = ffma2(md.x, x3, acc[p0][3]);
                acc[p0+1][0] = ffma2(md.y, x0, acc[p0+1][0]);
                acc[p0+1][1] = ffma2(md.y, x1, acc[p0+1][1]);
                acc[p0+1][2] = ffma2(md.y, x2, acc[p0+1][2]);
                acc[p0+1][3] = ffma2(md.y, x3, acc[p0+1][3]);
            }
        }
    }

    if (colok) {
        float4* yp = Y + c4;
#pragma unroll
        for (int p = 0; p < 4; ++p) {
            float a0, b0, a1, b1, a2, b2, a3, b3;
            unpack2(acc[p][0], a0, b0);
            unpack2(acc[p][1], a1, b1);
            unpack2(acc[p][2], a2, b2);
            unpack2(acc[p][3], a3, b3);
            const int r0 = ty * 8 + 2 * p;
            yp[(long)r0 * NC4]       = make_float4(a0, a1, a2, a3);
            yp[(long)(r0 + 1) * NC4] = make_float4(b0, b1, b2, b3);
        }
    }
}

// ---------------------------------------------------------------------------
extern "C" void kernel_launch(void* const* d_in, const int* in_sizes, int n_in,
                              void* d_out, int out_size) {
    const float* X      = (const float*)d_in[0];
    const float* angles = (const float*)d_in[1];
    const float* mus    = (const float*)d_in[2];
    float* Y = (float*)d_out;

    build_M_kernel<<<1, 64>>>(angles, mus);

    const int grid = (NC4 + CW - 1) / CW;   // 3907
    gemm_kernel<<<grid, 256>>>((const float4*)X, (float4*)Y);
}

// round 11
// speedup vs baseline: 2.1140x; 1.0529x over previous
#include <cuda_runtime.h>
#include <stdint.h>

#define NPT  64
#define NC   500000
#define NC4  125000      // NC/4 float4 columns
#define NANG 2016        // 64*63/2
#define KC   16          // k-rows per cp.async chunk
#define NBUF 3           // pipeline depth
#define NCHUNK (NPT/KC)  // 4
#define CW   32          // float4 columns per block
#define PF   4           // prefetch depth in build_M

// g_Mt[k*64 + i] = mus[i] * M[i][k]
__device__ __align__(16) float g_Mt[NPT * NPT];

// ---------------------------------------------------------------------------
// Kernel 1: build the composite 64x64 rotation matrix.
// Depth-4 register prefetch with PADDED shared arrays so every prefetch is
// UNPREDICATED (R7's version clamped with ISETP -> @P LDS: 13-cyc
// pred-as-guard latency x2 per rotation was the 40us overhead). Pad values
// are loaded into the rolling buffers but never consumed.
// ---------------------------------------------------------------------------
__global__ void __launch_bounds__(64) build_M_kernel(const float* __restrict__ angles,
                                                     const float* __restrict__ mus) {
    __shared__ float2 scs[NANG + PF];     // (cos, sin)
    __shared__ float  sm[NPT + PF][NPT];  // [row][col], 4 pad rows
    const int t = threadIdx.x;

    for (int a = t; a < NANG; a += 64) {
        float s, c;
        sincosf(angles[a], &s, &c);
        scs[a] = make_float2(c, s);
    }
    if (t < PF) scs[NANG + t] = make_float2(1.f, 0.f);
#pragma unroll
    for (int i = 0; i < NPT; ++i) sm[i][t] = (i == t) ? 1.0f : 0.0f;
#pragma unroll
    for (int i = 0; i < PF; ++i) sm[NPT + i][t] = 0.0f;
    __syncthreads();

    int a = 0;
    for (int it = 0; it < NPT - 1; ++it) {
        float vt = sm[it][t];
        // prime depth-4 prefetch — all in-bounds thanks to padding
        float vb0 = sm[it + 1][t];
        float vb1 = sm[it + 2][t];
        float vb2 = sm[it + 3][t];
        float vb3 = sm[it + 4][t];
        float2 cs0 = scs[a];
        float2 cs1 = scs[a + 1];
        float2 cs2 = scs[a + 2];
        float2 cs3 = scs[a + 3];

#pragma unroll 4
        for (int ib = it + 1; ib < NPT; ++ib) {
            const float c = cs0.x;
            const float s = cs0.y;
            const float vb = vb0;
            vb0 = vb1; vb1 = vb2; vb2 = vb3;
            cs0 = cs1; cs1 = cs2; cs2 = cs3;
            vb3 = sm[ib + 4][t];     // unconditional (pad rows, never consumed)
            cs3 = scs[a + 4];        // unconditional (pad entries, never consumed)

            sm[ib][t] = fmaf(s, vt, c * vb);   // off-chain
            vt = fmaf(c, vt, -s * vb);         // 4-cyc chain
            ++a;
        }
        sm[it][t] = vt;
    }
    // thread t wrote column t; it alone reads it back -> no sync needed.
    for (int i = 0; i < NPT; ++i) g_Mt[t * NPT + i] = sm[i][t] * __ldg(&mus[i]);
}

// ---------------------------------------------------------------------------
// Packed f32x2 helpers (FFMA2).
// ---------------------------------------------------------------------------
typedef unsigned long long u64;

__device__ __forceinline__ u64 ffma2(u64 a, u64 b, u64 c) {
    u64 d;
    asm("fma.rn.f32x2 %0, %1, %2, %3;" : "=l"(d) : "l"(a), "l"(b), "l"(c));
    return d;
}
__device__ __forceinline__ u64 pack2(float lo, float hi) {
    u64 d;
    asm("mov.b64 %0, {%1, %2};" : "=l"(d) : "f"(lo), "f"(hi));
    return d;
}
__device__ __forceinline__ void unpack2(u64 d, float& lo, float& hi) {
    asm("mov.b64 {%0, %1}, %2;" : "=f"(lo), "=f"(hi) : "l"(d));
}

// ---------------------------------------------------------------------------
// cp.async helpers
// ---------------------------------------------------------------------------
__device__ __forceinline__ void cp_async16(uint32_t smem_dst, const void* gsrc, int src_bytes) {
    asm volatile("cp.async.cg.shared.global [%0], [%1], 16, %2;"
                 :: "r"(smem_dst), "l"(gsrc), "r"(src_bytes));
}
__device__ __forceinline__ void cp_commit() {
    asm volatile("cp.async.commit_group;");
}

// Issue one KC x CW-float4 chunk (8KB): 2 cp.async per thread.
__device__ __forceinline__ void issue_chunk(const float4* __restrict__ X,
                                            float4 (*sX)[KC][CW],
                                            long cb, int tid, int ch, int buf) {
#pragma unroll
    for (int r = 0; r < (KC * CW) / 256; ++r) {
        const int e = tid + r * 256;
        const int k = e / CW;
        const int c = e % CW;
        const long col = cb + c;
        const bool ok = (col < NC4);
        const float4* src = X + (long)(ch * KC + k) * NC4 + (ok ? col : 0);
        const uint32_t dst = (uint32_t)__cvta_generic_to_shared(&sX[buf][k][c]);
        cp_async16(dst, src, ok ? 16 : 0);   // zfill on OOB columns
    }
    cp_commit();
}

// ---------------------------------------------------------------------------
// Kernel 2: Y = (diag(mus)*M) @ X.  (unchanged — at FFMA2-pipe plateau)
// ---------------------------------------------------------------------------
__global__ void __launch_bounds__(256, 3) gemm_kernel(const float4* __restrict__ X,
                                                      float4* __restrict__ Y) {
    __shared__ __align__(16) float  sM[NPT * NPT];        // 16 KB
    __shared__ __align__(16) float4 sX[NBUF][KC][CW];     // 24 KB

    const int tid = threadIdx.x;
#pragma unroll
    for (int i = 0; i < 4; ++i)
        ((float4*)sM)[tid + i * 256] = ((const float4*)g_Mt)[tid + i * 256];

    const int tx = tid & 31;
    const int ty = tid >> 5;                 // rows [ty*8, ty*8+8)
    const long cb = (long)blockIdx.x * CW;
    const long c4 = cb + tx;
    const bool colok = (c4 < NC4);

    issue_chunk(X, sX, cb, tid, 0, 0);
    issue_chunk(X, sX, cb, tid, 1, 1);

    u64 acc[4][4];
#pragma unroll
    for (int p = 0; p < 4; ++p)
#pragma unroll
        for (int c = 0; c < 4; ++c) acc[p][c] = 0ULL;

    for (int ch = 0; ch < NCHUNK; ++ch) {
        asm volatile("cp.async.wait_group %0;" :: "n"(NBUF - 2));
        __syncthreads();   // ch visible to all; all done reading buf (ch-1)%NBUF

        const int nxt = ch + NBUF - 1;
        if (nxt < NCHUNK) issue_chunk(X, sX, cb, tid, nxt, nxt % NBUF);
        else              cp_commit();     // empty group keeps wait counts aligned

        const int buf = ch % NBUF;
#pragma unroll
        for (int k = 0; k < KC; ++k) {
            const float4 xv = sX[buf][k][tx];
            const u64 x0 = pack2(xv.x, xv.x);
            const u64 x1 = pack2(xv.y, xv.y);
            const u64 x2 = pack2(xv.z, xv.z);
            const u64 x3 = pack2(xv.w, xv.w);

            const ulonglong2* mp = (const ulonglong2*)&sM[(ch * KC + k) * NPT + ty * 8];
#pragma unroll
            for (int pq = 0; pq < 2; ++pq) {
                const ulonglong2 md = mp[pq];    // broadcast LDS.128: rows 4pq..4pq+3
                const int p0 = 2 * pq;
                acc[p0][0]   = ffma2(md.x, x0, acc[p0][0]);
                acc[p0][1]   = ffma2(md.x, x1, acc[p0][1]);
                acc[p0][2]   = ffma2(md.x, x2, acc[p0][2]);
                acc[p0][3]   = ffma2(md.x, x3, acc[p0][3]);
                acc[p0+1][0] = ffma2(md.y, x0, acc[p0+1][0]);
                acc[p0+1][1] = ffma2(md.y, x1, acc[p0+1][1]);
                acc[p0+1][2] = ffma2(md.y, x2, acc[p0+1][2]);
                acc[p0+1][3] = ffma2(md.y, x3, acc[p0+1][3]);
            }
        }
    }

    if (colok) {
        float4* yp = Y + c4;
#pragma unroll
        for (int p = 0; p < 4; ++p) {
            float a0, b0, a1, b1, a2, b2, a3, b3;
            unpack2(acc[p][0], a0, b0);
            unpack2(acc[p][1], a1, b1);
            unpack2(acc[p][2], a2, b2);
            unpack2(acc[p][3], a3, b3);
            const int r0 = ty * 8 + 2 * p;
            yp[(long)r0 * NC4]       = make_float4(a0, a1, a2, a3);
            yp[(long)(r0 + 1) * NC4] = make_float4(b0, b1, b2, b3);
        }
    }
}

// ---------------------------------------------------------------------------
extern "C" void kernel_launch(void* const* d_in, const int* in_sizes, int n_in,
                              void* d_out, int out_size) {
    const float* X      = (const float*)d_in[0];
    const float* angles = (const float*)d_in[1];
    const float* mus    = (const float*)d_in[2];
    float* Y = (float*)d_out;

    build_M_kernel<<<1, 64>>>(angles, mus);

    const int grid = (NC4 + CW - 1) / CW;   // 3907
    gemm_kernel<<<grid, 256>>>((const float4*)X, (float4*)Y);
}

// round 12
// speedup vs baseline: 2.3344x; 1.1042x over previous
#include <cuda_runtime.h>
#include <stdint.h>

#define NPT  64
#define NC   500000
#define NC4  125000      // NC/4 float4 columns
#define NANG 2016        // 64*63/2
#define KC   16          // k-rows per cp.async chunk
#define NBUF 3           // pipeline depth
#define NCHUNK (NPT/KC)  // 4
#define CW   32          // float4 columns per block
#define G    8           // Givens passes per group in build_M

// g_Mt[k*64 + i] = mus[i] * M[i][k]
__device__ __align__(16) float g_Mt[NPT * NPT];

// ---------------------------------------------------------------------------
// Kernel 1: build the composite 64x64 rotation matrix.
// BLOCKED CASCADE: 8 passes applied per row sweep. Row value w flows through
// the 8 rotations in registers (pass j's output row == pass j+1's input row),
// vt[j] register-carried per pass. 8x fewer row LDS/STS than one-pass-at-a-
// time, and 8 independent FMA chains per step -> issue-bound, not
// latency-bound. Peeled head rows handle pass-entry edges with compile-time
// predicates.
// ---------------------------------------------------------------------------
__global__ void __launch_bounds__(64) build_M_kernel(const float* __restrict__ angles,
                                                     const float* __restrict__ mus) {
    __shared__ float2 scs[NANG];          // (cos, sin)
    __shared__ float  sm[NPT + 1][NPT];   // [row][col], +1 pad row for prefetch
    const int t = threadIdx.x;

    for (int a = t; a < NANG; a += 64) {
        float s, c;
        sincosf(angles[a], &s, &c);
        scs[a] = make_float2(c, s);
    }
    // identity column t (per-thread private column: no sync needed for sm)
#pragma unroll
    for (int i = 0; i < NPT; ++i) sm[i][t] = (i == t) ? 1.0f : 0.0f;
    sm[NPT][t] = 0.0f;
    __syncthreads();    // scs visible

    for (int g = 0; g < NPT / G; ++g) {
        const int b = g * G;
        // angle-table base per stage: idx(it, ib) = 63*it - it*(it-1)/2 - it - 1 + ib
        int aj[G];
#pragma unroll
        for (int j = 0; j < G; ++j) {
            const int it = b + j;
            aj[j] = 63 * it - (it * (it - 1)) / 2 - it - 1;
        }

        float vt[G];
        vt[0] = sm[b][t];                 // pass b starts from row b (post pass b-1)

        // ---- peel rows r = b+1 .. b+G-1 (stage-entry edges, compile-time preds)
#pragma unroll
        for (int rr = 1; rr < G; ++rr) {
            const int r = b + rr;
            float w = sm[r][t];
#pragma unroll
            for (int j = 0; j < G; ++j) {
                if (j < rr) {
                    const float2 cs = scs[aj[j] + r];
                    const float out = fmaf(cs.y, vt[j], cs.x * w);
                    vt[j] = fmaf(cs.x, vt[j], -cs.y * w);
                    w = out;
                } else if (j == rr) {
                    vt[j] = w;            // row r graduates into pass b+rr
                }
            }
            // r <= b+G-1: row became a vt, nothing stored
        }

        // ---- main rows r = b+G .. 63 (all 8 stages active)
        if (b + G < NPT) {
            float w = sm[b + G][t];
            for (int r = b + G; r < NPT; ++r) {
                const float wn = sm[r + 1][t];   // unconditional prefetch (pad row)
#pragma unroll
                for (int j = 0; j < G; ++j) {
                    const float2 cs = scs[aj[j] + r];
                    const float out = fmaf(cs.y, vt[j], cs.x * w);
                    vt[j] = fmaf(cs.x, vt[j], -cs.y * w);
                    w = out;
                }
                sm[r][t] = w;             // post-pass-(b+G-1) value
                w = wn;
            }
        }

        // ---- rows b..b+G-1 are final for this group
#pragma unroll
        for (int j = 0; j < G; ++j) sm[b + j][t] = vt[j];
    }

    // thread t owns column t end-to-end: no sync needed.
    for (int i = 0; i < NPT; ++i) g_Mt[t * NPT + i] = sm[i][t] * __ldg(&mus[i]);
}

// ---------------------------------------------------------------------------
// Packed f32x2 helpers (FFMA2).
// ---------------------------------------------------------------------------
typedef unsigned long long u64;

__device__ __forceinline__ u64 ffma2(u64 a, u64 b, u64 c) {
    u64 d;
    asm("fma.rn.f32x2 %0, %1, %2, %3;" : "=l"(d) : "l"(a), "l"(b), "l"(c));
    return d;
}
__device__ __forceinline__ u64 pack2(float lo, float hi) {
    u64 d;
    asm("mov.b64 %0, {%1, %2};" : "=l"(d) : "f"(lo), "f"(hi));
    return d;
}
__device__ __forceinline__ void unpack2(u64 d, float& lo, float& hi) {
    asm("mov.b64 {%0, %1}, %2;" : "=f"(lo), "=f"(hi) : "l"(d));
}

// ---------------------------------------------------------------------------
// cp.async helpers
// ---------------------------------------------------------------------------
__device__ __forceinline__ void cp_async16(uint32_t smem_dst, const void* gsrc, int src_bytes) {
    asm volatile("cp.async.cg.shared.global [%0], [%1], 16, %2;"
                 :: "r"(smem_dst), "l"(gsrc), "r"(src_bytes));
}
__device__ __forceinline__ void cp_commit() {
    asm volatile("cp.async.commit_group;");
}

// Issue one KC x CW-float4 chunk (8KB): 2 cp.async per thread.
__device__ __forceinline__ void issue_chunk(const float4* __restrict__ X,
                                            float4 (*sX)[KC][CW],
                                            long cb, int tid, int ch, int buf) {
#pragma unroll
    for (int r = 0; r < (KC * CW) / 256; ++r) {
        const int e = tid + r * 256;
        const int k = e / CW;
        const int c = e % CW;
        const long col = cb + c;
        const bool ok = (col < NC4);
        const float4* src = X + (long)(ch * KC + k) * NC4 + (ok ? col : 0);
        const uint32_t dst = (uint32_t)__cvta_generic_to_shared(&sX[buf][k][c]);
        cp_async16(dst, src, ok ? 16 : 0);   // zfill on OOB columns
    }
    cp_commit();
}

// ---------------------------------------------------------------------------
// Kernel 2: Y = (diag(mus)*M) @ X.  (unchanged — at FFMA2-pipe plateau)
// ---------------------------------------------------------------------------
__global__ void __launch_bounds__(256, 3) gemm_kernel(const float4* __restrict__ X,
                                                      float4* __restrict__ Y) {
    __shared__ __align__(16) float  sM[NPT * NPT];        // 16 KB
    __shared__ __align__(16) float4 sX[NBUF][KC][CW];     // 24 KB

    const int tid = threadIdx.x;
#pragma unroll
    for (int i = 0; i < 4; ++i)
        ((float4*)sM)[tid + i * 256] = ((const float4*)g_Mt)[tid + i * 256];

    const int tx = tid & 31;
    const int ty = tid >> 5;                 // rows [ty*8, ty*8+8)
    const long cb = (long)blockIdx.x * CW;
    const long c4 = cb + tx;
    const bool colok = (c4 < NC4);

    issue_chunk(X, sX, cb, tid, 0, 0);
    issue_chunk(X, sX, cb, tid, 1, 1);

    u64 acc[4][4];
#pragma unroll
    for (int p = 0; p < 4; ++p)
#pragma unroll
        for (int c = 0; c < 4; ++c) acc[p][c] = 0ULL;

    for (int ch = 0; ch < NCHUNK; ++ch) {
        asm volatile("cp.async.wait_group %0;" :: "n"(NBUF - 2));
        __syncthreads();   // ch visible to all; all done reading buf (ch-1)%NBUF

        const int nxt = ch + NBUF - 1;
        if (nxt < NCHUNK) issue_chunk(X, sX, cb, tid, nxt, nxt % NBUF);
        else              cp_commit();     // empty group keeps wait counts aligned

        const int buf = ch % NBUF;
#pragma unroll
        for (int k = 0; k < KC; ++k) {
            const float4 xv = sX[buf][k][tx];
            const u64 x0 = pack2(xv.x, xv.x);
            const u64 x1 = pack2(xv.y, xv.y);
            const u64 x2 = pack2(xv.z, xv.z);
            const u64 x3 = pack2(xv.w, xv.w);

            const ulonglong2* mp = (const ulonglong2*)&sM[(ch * KC + k) * NPT + ty * 8];
#pragma unroll
            for (int pq = 0; pq < 2; ++pq) {
                const ulonglong2 md = mp[pq];    // broadcast LDS.128: rows 4pq..4pq+3
                const int p0 = 2 * pq;
                acc[p0][0]   = ffma2(md.x, x0, acc[p0][0]);
                acc[p0][1]   = ffma2(md.x, x1, acc[p0][1]);
                acc[p0][2]   = ffma2(md.x, x2, acc[p0][2]);
                acc[p0][3]   = ffma2(md.x, x3, acc[p0][3]);
                acc[p0+1][0] = ffma2(md.y, x0, acc[p0+1][0]);
                acc[p0+1][1] = ffma2(md.y, x1, acc[p0+1][1]);
                acc[p0+1][2] = ffma2(md.y, x2, acc[p0+1][2]);
                acc[p0+1][3] = ffma2(md.y, x3, acc[p0+1][3]);
            }
        }
    }

    if (colok) {
        float4* yp = Y + c4;
#pragma unroll
        for (int p = 0; p < 4; ++p) {
            float a0, b0, a1, b1, a2, b2, a3, b3;
            unpack2(acc[p][0], a0, b0);
            unpack2(acc[p][1], a1, b1);
            unpack2(acc[p][2], a2, b2);
            unpack2(acc[p][3], a3, b3);
            const int r0 = ty * 8 + 2 * p;
            yp[(long)r0 * NC4]       = make_float4(a0, a1, a2, a3);
            yp[(long)(r0 + 1) * NC4] = make_float4(b0, b1, b2, b3);
        }
    }
}

// ---------------------------------------------------------------------------
extern "C" void kernel_launch(void* const* d_in, const int* in_sizes, int n_in,
                              void* d_out, int out_size) {
    const float* X      = (const float*)d_in[0];
    const float* angles = (const float*)d_in[1];
    const float* mus    = (const float*)d_in[2];
    float* Y = (float*)d_out;

    build_M_kernel<<<1, 64>>>(angles, mus);

    const int grid = (NC4 + CW - 1) / CW;   // 3907
    gemm_kernel<<<grid, 256>>>((const float4*)X, (float4*)Y);
}